// round 8
// baseline (speedup 1.0000x reference)
#include <cuda_runtime.h>
#include <cuda_bf16.h>
#include <math.h>
#include <stdint.h>

// Problem constants
#define NH 6
#define NN 64   // rows of A tile (n)
#define NK 64   // inner dim (k)
#define ND 30   // cols of B tile (d)

#define NBYA 256   // batch/16 partial blocks for A
#define NBYB 128   // batch/32 partial blocks for B

// ---------------- scratch (device globals; no atomics, no init needed) -------
__device__ float g_pAmin[NBYA*NH*NK], g_pAmax[NBYA*NH*NK];
__device__ float g_pBmin[NBYB*NH*ND], g_pBmax[NBYB*NH*ND];
__device__ __align__(16) float g_dA[NH*NK], g_zA[NH*NK], g_iA[NH*NK];
__device__ __align__(16) float g_dB[NH*ND], g_zB[NH*ND], g_iB[NH*ND];

// ---------------- small PTX helpers (base-target legal) ----------------------
__device__ __forceinline__ uint32_t smem_to_u32(const void* p) {
    uint32_t a;
    asm("{ .reg .u64 tmp; cvta.to.shared.u64 tmp, %1; cvt.u32.u64 %0, tmp; }"
        : "=r"(a) : "l"(p));
    return a;
}
__device__ __forceinline__ void ldsm_x4(uint32_t* r, uint32_t addr) {
    asm volatile("ldmatrix.sync.aligned.m8n8.x4.shared.b16 {%0,%1,%2,%3}, [%4];"
                 : "=r"(r[0]), "=r"(r[1]), "=r"(r[2]), "=r"(r[3]) : "r"(addr));
}
__device__ __forceinline__ void mma_bf16(float* c, const uint32_t* a,
                                         const uint32_t* b) {
    asm volatile(
        "mma.sync.aligned.m16n8k16.row.col.f32.bf16.bf16.f32 "
        "{%0,%1,%2,%3}, {%4,%5,%6,%7}, {%8,%9}, {%0,%1,%2,%3};"
        : "+f"(c[0]), "+f"(c[1]), "+f"(c[2]), "+f"(c[3])
        : "r"(a[0]), "r"(a[1]), "r"(a[2]), "r"(a[3]), "r"(b[0]), "r"(b[1]));
}
#define SWZ128(off) ((off) ^ (((off) >> 3) & 0x70))

// round-to-nearest-even via magic constant (valid |y| < 2^22); 2 FADDs
__device__ __forceinline__ float rne(float y) {
    const float M = 12582912.0f;   // 1.5 * 2^23
    return __fadd_rn(__fadd_rn(y, M), -M);
}

// ---------------- kernel 1a: partial min/max of A ----------------------------
__global__ __launch_bounds__(256) void k_minmax_A(const float* __restrict__ A,
                                                  int batch, int bpb) {
    int h  = blockIdx.x;
    int by = blockIdx.y;
    int b0 = by * bpb;
    int t  = threadIdx.x;
    int k0 = (t & 15) * 4;
    float4 mn = make_float4( INFINITY,  INFINITY,  INFINITY,  INFINITY);
    float4 mx = make_float4(-INFINITY, -INFINITY, -INFINITY, -INFINITY);
    for (int bi = 0; bi < bpb; ++bi) {
        int b = b0 + bi;
        if (b >= batch) break;
        const float4* p = (const float4*)(A + ((size_t)b * NH + h) * (NN*NK));
        #pragma unroll
        for (int it = 0; it < 4; ++it) {
            float4 v = p[it * 256 + t];
            mn.x = fminf(mn.x, v.x); mx.x = fmaxf(mx.x, v.x);
            mn.y = fminf(mn.y, v.y); mx.y = fmaxf(mx.y, v.y);
            mn.z = fminf(mn.z, v.z); mx.z = fmaxf(mx.z, v.z);
            mn.w = fminf(mn.w, v.w); mx.w = fmaxf(mx.w, v.w);
        }
    }
    __shared__ float smn[64*17], smx[64*17];
    int col = t >> 4;
    smn[(k0+0)*17 + col] = mn.x; smx[(k0+0)*17 + col] = mx.x;
    smn[(k0+1)*17 + col] = mn.y; smx[(k0+1)*17 + col] = mx.y;
    smn[(k0+2)*17 + col] = mn.z; smx[(k0+2)*17 + col] = mx.z;
    smn[(k0+3)*17 + col] = mn.w; smx[(k0+3)*17 + col] = mx.w;
    __syncthreads();
    if (t < 64) {
        float a = INFINITY, b = -INFINITY;
        #pragma unroll
        for (int c = 0; c < 16; ++c) {
            a = fminf(a, smn[t*17 + c]);
            b = fmaxf(b, smx[t*17 + c]);
        }
        int idx = by * (NH*NK) + h * NK + t;
        g_pAmin[idx] = a;
        g_pAmax[idx] = b;
    }
}

// ---------------- kernel 1b: partial min/max of B ----------------------------
__global__ __launch_bounds__(480) void k_minmax_B(const float* __restrict__ B,
                                                  int batch, int bpb) {
    int h  = blockIdx.x;
    int by = blockIdx.y;
    int b0 = by * bpb;
    int t  = threadIdx.x;
    float mn = INFINITY, mx = -INFINITY;
    for (int bi = 0; bi < bpb; ++bi) {
        int b = b0 + bi;
        if (b >= batch) break;
        const float* p = B + ((size_t)b * NH + h) * (NK*ND);
        #pragma unroll
        for (int it = 0; it < 4; ++it) {
            float v = p[it * 480 + t];
            mn = fminf(mn, v); mx = fmaxf(mx, v);
        }
    }
    __shared__ float smn[30*17], smx[30*17];
    int d = t % 30, g = t / 30;
    smn[d*17 + g] = mn; smx[d*17 + g] = mx;
    __syncthreads();
    if (t < 30) {
        float a = INFINITY, b = -INFINITY;
        #pragma unroll
        for (int c = 0; c < 16; ++c) {
            a = fminf(a, smn[t*17 + c]);
            b = fmaxf(b, smx[t*17 + c]);
        }
        int idx = by * (NH*ND) + h * ND + t;
        g_pBmin[idx] = a;
        g_pBmax[idx] = b;
    }
}

// ---------------- kernel 2: reduce partials + quant params -------------------
__global__ __launch_bounds__(384) void k_params(int nbyA, int nbyB) {
    int i = threadIdx.x;
    if (blockIdx.x == 0) {
        // A channels: i in [0, 384)
        float mn = INFINITY, mx = -INFINITY;
        for (int b = 0; b < nbyA; ++b) {
            mn = fminf(mn, g_pAmin[b * (NH*NK) + i]);
            mx = fmaxf(mx, g_pAmax[b * (NH*NK) + i]);
        }
        float d = fmaxf((mx - mn) / 255.0f, 1e-8f);
        float z = rintf(-mn / d);
        g_dA[i] = d; g_zA[i] = z; g_iA[i] = 1.0f / d;
    } else {
        if (i < NH*ND) {
            float mn = INFINITY, mx = -INFINITY;
            for (int b = 0; b < nbyB; ++b) {
                mn = fminf(mn, g_pBmin[b * (NH*ND) + i]);
                mx = fmaxf(mx, g_pBmax[b * (NH*ND) + i]);
            }
            float d = fmaxf((mx - mn) / 255.0f, 1e-8f);
            float z = rintf(-mn / d);
            g_dB[i] = d; g_zB[i] = z; g_iB[i] = 1.0f / d;
        }
    }
}

// fake-quant returning the integer (q-zp)  (exact fp32, low mantissa zero)
__device__ __forceinline__ float fqi(float x, float dlt, float zp, float inv) {
    float y = x * inv;
    float r = rne(y);
    if (fabsf(fabsf(y - r) - 0.5f) < 1e-4f) r = rintf(x / dlt);
    return fminf(fmaxf(r + zp, 0.0f), 255.0f) - zp;
}

// ---------------- per-slice smem layout (bytes) ------------------------------
// Aint: 64 rows(m) x 128B (exact bf16 ints, SW128)  = 8192
// B'hi: 32 rows(d) x 128B (SW128)                   = 4096  (rows 30,31 unused)
// B'lo: 4096      B' = dA[k] * bint  (hi/lo split)
#define OFF_A   0
#define OFF_BHI 8192
#define OFF_BLO 12288
#define SLICE_BYTES 16384
#define SMEM_DYN (2*SLICE_BYTES + 1024)

// ---------------- kernel 3: int-A bf16 MMA quantized matmul ------------------
// One block per PAIR of (b,h) slices; 8 warps, warps 0-3 slice0, 4-7 slice1.
// D = Aint @ (B'hi + B'lo), epilogue scales by dB[d].
__global__ __launch_bounds__(256, 4)
void k_qmm_mma(const float* __restrict__ A, const float* __restrict__ B,
               float* __restrict__ C) {
    extern __shared__ char raw[];
    char* sm = (char*)(((uintptr_t)raw + 1023) & ~(uintptr_t)1023);
    uint32_t sb = smem_to_u32(sm);

    int t = threadIdx.x;
    int p = blockIdx.x;
    int s0 = 2 * p;
    int h0 = s0 % NH, h1 = (s0 + 1) % NH;

    // ---- A: quantize to exact bf16 integers (top-16 shift, no cvt) ----
    const float4* Ap = (const float4*)(A + (size_t)s0 * (NN*NK));
    int k0 = (4 * t) & 63;
    #pragma unroll
    for (int j = 0; j < 2; ++j) {
        int hb = (j ? h1 : h0) * NK + k0;
        float4 d4 = __ldg((const float4*)&g_dA[hb]);
        float4 z4 = __ldg((const float4*)&g_zA[hb]);
        float4 i4 = __ldg((const float4*)&g_iA[hb]);
        char* base = sm + j * SLICE_BYTES;
        #pragma unroll
        for (int it = 0; it < 4; ++it) {
            int idx = (j * 4 + it) * 256 + t;
            float4 v = Ap[idx];
            int m = (idx & 1023) >> 4;
            float a0 = fqi(v.x, d4.x, z4.x, i4.x);
            float a1 = fqi(v.y, d4.y, z4.y, i4.y);
            float a2 = fqi(v.z, d4.z, z4.z, i4.z);
            float a3 = fqi(v.w, d4.w, z4.w, i4.w);
            // integers exact in bf16: top-16-bit truncation is lossless
            uint32_t u0 = __float_as_uint(a0), u1 = __float_as_uint(a1);
            uint32_t u2 = __float_as_uint(a2), u3 = __float_as_uint(a3);
            uint32_t p01 = __byte_perm(u0, u1, 0x7632);
            uint32_t p23 = __byte_perm(u2, u3, 0x7632);
            uint32_t off = SWZ128((uint32_t)(m * 128 + k0 * 2));
            *(uint2*)(base + OFF_A + off) = make_uint2(p01, p23);
        }
    }

    // ---- B: quantize, scale by dA[k], hi/lo split, store [d][k] SW128 ----
    const float* Bp = B + (size_t)s0 * (NK*ND);
    #pragma unroll
    for (int it = 0; it < 15; ++it) {
        int e = it * 256 + t;
        float x = Bp[e];
        int j  = (e >= NK*ND);
        int e2 = e - j * (NK*ND);
        int k  = e2 / ND, d = e2 % ND;
        int h  = j ? h1 : h0;
        float bi = fqi(x, __ldg(&g_dB[h*ND + d]), __ldg(&g_zB[h*ND + d]),
                       __ldg(&g_iB[h*ND + d]));
        float bp = bi * __ldg(&g_dA[h*NK + k]);
        uint32_t ub = __float_as_uint(bp);
        float lo = bp - __uint_as_float(ub & 0xFFFF0000u);
        uint32_t off = SWZ128((uint32_t)(d * 128 + k * 2));
        char* base = sm + j * SLICE_BYTES;
        *(uint16_t*)(base + OFF_BHI + off) = (uint16_t)(ub >> 16);
        *(__nv_bfloat16*)(base + OFF_BLO + off) = __float2bfloat16(lo);
    }
    __syncthreads();

    // ---- compute: warp = 16 rows x 32 cols, mma.sync m16n8k16 bf16 ----
    int w = t >> 5, lane = t & 31;
    int sj = w >> 2;          // slice
    int ws = w & 3;           // warp within slice
    int r0 = ws * 16;
    uint32_t baseS = sb + sj * SLICE_BYTES;

    int la = lane & 7, lb = (lane >> 3) & 1, lc = (lane >> 4) & 1;
    uint32_t aRel = (uint32_t)((r0 + la + lb * 8) * 128 + lc * 16);
    uint32_t bRel = (uint32_t)((la + lc * 8) * 128 + lb * 16);

    float acc[4][4];
    #pragma unroll
    for (int i = 0; i < 4; ++i)
        #pragma unroll
        for (int q = 0; q < 4; ++q) acc[i][q] = 0.0f;

    #pragma unroll
    for (int kt = 0; kt < 4; ++kt) {
        uint32_t ko = kt * 32;
        uint32_t a4[4], bh0[4], bh1[4], bl0[4], bl1[4];
        ldsm_x4(a4, baseS + OFF_A + SWZ128(aRel + ko));
        uint32_t bo0 = SWZ128(bRel + ko), bo1 = SWZ128(bRel + 2048 + ko);
        ldsm_x4(bh0, baseS + OFF_BHI + bo0);      // d 0..15
        ldsm_x4(bh1, baseS + OFF_BHI + bo1);      // d 16..31
        ldsm_x4(bl0, baseS + OFF_BLO + bo0);
        ldsm_x4(bl1, baseS + OFF_BLO + bo1);
        mma_bf16(acc[0], a4, bh0 + 0); mma_bf16(acc[0], a4, bl0 + 0);
        mma_bf16(acc[1], a4, bh0 + 2); mma_bf16(acc[1], a4, bl0 + 2);
        mma_bf16(acc[2], a4, bh1 + 0); mma_bf16(acc[2], a4, bl1 + 0);
        mma_bf16(acc[3], a4, bh1 + 2); mma_bf16(acc[3], a4, bl1 + 2);
    }

    // ---- epilogue: scale by dB[d], float2 writes ----
    int s  = s0 + sj;
    int h  = s % NH;
    int row = r0 + (lane >> 2);
    int dd  = 2 * (lane & 3);
    float* Cp = C + (size_t)s * (NN*ND);
    #pragma unroll
    for (int nt = 0; nt < 4; ++nt) {
        int d = nt * 8 + dd;
        if (d < ND) {
            float sc0 = __ldg(&g_dB[h*ND + d]);
            float sc1 = __ldg(&g_dB[h*ND + d + 1]);
            *(float2*)(Cp + row * ND + d) =
                make_float2(acc[nt][0] * sc0, acc[nt][1] * sc1);
            *(float2*)(Cp + (row + 8) * ND + d) =
                make_float2(acc[nt][2] * sc0, acc[nt][3] * sc1);
        }
    }
}

// ---------------- launch -----------------------------------------------------
extern "C" void kernel_launch(void* const* d_in, const int* in_sizes, int n_in,
                              void* d_out, int out_size) {
    const float* A = (const float*)d_in[0];
    const float* B = (const float*)d_in[1];
    float* C = (float*)d_out;

    int batch  = in_sizes[0] / (NH * NN * NK);   // 4096
    int npairs = batch * NH / 2;                 // 12288

    int bpbA = (batch + NBYA - 1) / NBYA;        // 16
    k_minmax_A<<<dim3(NH, NBYA), 256>>>(A, batch, bpbA);

    int bpbB = (batch + NBYB - 1) / NBYB;        // 32
    k_minmax_B<<<dim3(NH, NBYB), 480>>>(B, batch, bpbB);

    k_params<<<2, 384>>>(NBYA, NBYB);

    cudaFuncSetAttribute(k_qmm_mma, cudaFuncAttributeMaxDynamicSharedMemorySize,
                         SMEM_DYN);
    k_qmm_mma<<<npairs, 256, SMEM_DYN>>>(A, B, C);
}